// round 16
// baseline (speedup 1.0000x reference)
#include <cuda_runtime.h>
#include <cuda_bf16.h>
#include <math.h>
#include <stdint.h>

// Problem constants
#define BB     8
#define SS     2048
#define CC     8
#define DD     9
#define WIN    60
#define NTOT   (BB * SS)      // 16384
#define SIGCH  285
#define KP1    288            // padded K for GEMM1 (9 chunks of 32)
#define H2C    512
#define H1C    256

// ---------------- scratch ----------------
__device__ __nv_bfloat16 g_fhi[(size_t)NTOT * KP1];
__device__ __nv_bfloat16 g_flo[(size_t)NTOT * KP1];
__device__ __nv_bfloat16 g_w1hi[KP1 * H2C];
__device__ __nv_bfloat16 g_w1lo[KP1 * H2C];
__device__ __nv_bfloat16 g_w2hi[H2C * H1C];
__device__ __nv_bfloat16 g_w2lo[H2C * H1C];

// ---------------- Lyndon tables ----------------
struct LyndonTab { short l2[36]; short l3[240]; };
constexpr LyndonTab make_tab() {
    LyndonTab t{};
    int n2 = 0, n3 = 0;
    for (int i = 0; i < DD; i++)
        for (int j = 0; j < DD; j++)
            if (i < j) t.l2[n2++] = (short)(i * 9 + j);
    for (int i = 0; i < DD; i++)
        for (int j = 0; j < DD; j++)
            for (int k = 0; k < DD; k++) {
                int e  = (i * 9 + j) * 9 + k;
                int r1 = (j * 9 + k) * 9 + i;
                int r2 = (k * 9 + i) * 9 + j;
                if (e < r1 && e < r2) t.l3[n3++] = (short)e;
            }
    return t;
}
__constant__ LyndonTab c_tab = make_tab();

// ---------------- helpers ----------------
__device__ __forceinline__ float gelu_exact(float v) {
    return 0.5f * v * (1.0f + erff(v * 0.70710678118654752f));
}
__device__ __forceinline__ void feat_store(int n, int idx, float v) {
    __nv_bfloat16 h = __float2bfloat16(v);
    g_fhi[(size_t)n * KP1 + idx] = h;
    g_flo[(size_t)n * KP1 + idx] = __float2bfloat16(v - __bfloat162float(h));
}
__device__ __forceinline__ uint32_t pkbf2(float a, float b) {
    __nv_bfloat162 t = __floats2bfloat162_rn(a, b);
    return *(uint32_t*)&t;
}
__device__ __forceinline__ uint32_t smem_u32(const void* p) {
    uint32_t a;
    asm("{ .reg .u64 t; cvta.to.shared.u64 t, %1; cvt.u32.u64 %0, t; }" : "=r"(a) : "l"(p));
    return a;
}
__device__ __forceinline__ void ldmx4(uint32_t* r, uint32_t addr) {
    asm volatile("ldmatrix.sync.aligned.m8n8.x4.shared.b16 {%0,%1,%2,%3}, [%4];"
                 : "=r"(r[0]), "=r"(r[1]), "=r"(r[2]), "=r"(r[3]) : "r"(addr));
}
__device__ __forceinline__ void ldmx4t(uint32_t* r, uint32_t addr) {
    asm volatile("ldmatrix.sync.aligned.m8n8.x4.trans.shared.b16 {%0,%1,%2,%3}, [%4];"
                 : "=r"(r[0]), "=r"(r[1]), "=r"(r[2]), "=r"(r[3]) : "r"(addr));
}
__device__ __forceinline__ void mma16816(float* d, const uint32_t* a,
                                         uint32_t b0, uint32_t b1) {
    asm volatile("mma.sync.aligned.m16n8k16.row.col.f32.bf16.bf16.f32 "
                 "{%0,%1,%2,%3}, {%4,%5,%6,%7}, {%8,%9}, {%0,%1,%2,%3};"
                 : "+f"(d[0]), "+f"(d[1]), "+f"(d[2]), "+f"(d[3])
                 : "r"(a[0]), "r"(a[1]), "r"(a[2]), "r"(a[3]), "r"(b0), "r"(b1));
}
__device__ __forceinline__ void cpa16(uint32_t dst, const void* src) {
    asm volatile("cp.async.cg.shared.global [%0], [%1], 16;" :: "r"(dst), "l"(src));
}
__device__ __forceinline__ void cpa_commit() {
    asm volatile("cp.async.commit_group;" ::: "memory");
}
template <int N>
__device__ __forceinline__ void cpa_wait() {
    asm volatile("cp.async.wait_group %0;" :: "n"(N) : "memory");
}

// ---------------------------------------------------------------------------
// Prep: bf16 hi/lo weights in natural [K][N] layout (K padded for w1).
// ---------------------------------------------------------------------------
__global__ void prep_kernel(const float* __restrict__ w1, const float* __restrict__ w2) {
    int idx = blockIdx.x * 256 + threadIdx.x;
    if (idx < KP1 * H2C) {
        int k = idx / H2C, n = idx - k * H2C;
        float v = (k < SIGCH) ? w1[(size_t)k * H2C + n] : 0.0f;
        __nv_bfloat16 h = __float2bfloat16(v);
        g_w1hi[idx] = h;
        g_w1lo[idx] = __float2bfloat16(v - __bfloat162float(h));
    } else {
        int j = idx - KP1 * H2C;
        if (j < H2C * H1C) {
            float v = w2[j];
            __nv_bfloat16 h = __float2bfloat16(v);
            g_w2hi[j] = h;
            g_w2lo[j] = __float2bfloat16(v - __bfloat162float(h));
        }
    }
}

// ---------------------------------------------------------------------------
// Kernel A (NEW): sliding-window log-signature.
// Window path = jump(v0) then 59 diff-increments G[ss..ss+58], where
//   G[m] = (1/59, 0) for m<59 ; (1/59, x[m-58]-x[m-59]) otherwise.
// Slide: R(ss+1) = exp(-G[ss]) (x) R(ss) (x) exp(G[ss+59]).
// Warp handles WPW consecutive windows: 59-step bootstrap, then 2 steps/window.
// Lanes 0..26: lane owns (i=lane/3, j in jb..jb+2): S3 rows in regs, S2 own
// rows in regs + full S2 mirrored in smem, full S1 replicated in regs.
// ---------------------------------------------------------------------------
#define WPW       16
#define SIG_WARPS 8
// per-warp smem layout (floats)
#define SIG_VB   0                 // 74 increments x 12
#define SIG_S3W  888               // 729 (W3 extract buffer)
#define SIG_S2S  1620              // 81  (R.S2 mirror)
#define SIG_S2W  1704              // 81  (W2 extract buffer)
#define SIG_S1W  1788              // 12  (W1 extract buffer)
#define SIG_WS   1800
#define SIG_SMEM (SIG_WS * SIG_WARPS * 4)   // 57600 B

__global__ __launch_bounds__(256) void sig_kernel(const float* __restrict__ x) {
    extern __shared__ float sgm[];
    const int w    = threadIdx.x >> 5;
    const int lane = threadIdx.x & 31;
    float* vbuf = sgm + w * SIG_WS + SIG_VB;
    float* s3w  = sgm + w * SIG_WS + SIG_S3W;
    float* s2s  = sgm + w * SIG_WS + SIG_S2S;
    float* s2w  = sgm + w * SIG_WS + SIG_S2W;
    float* s1w  = sgm + w * SIG_WS + SIG_S1W;

    const int ws  = (blockIdx.x * SIG_WARPS + w) * WPW;   // first window (global)
    const int bb  = ws >> 11;
    const int wsr = ws & 2047;                             // in-row start
    const float* xrow = x + (size_t)bb * SS * CC;
    const float inv59 = 1.0f / 59.0f;

    // ---- stage increments G[wsr+m], m=0..73 ----
    for (int m = lane; m < 74; m += 32) {
        int gm = wsr + m;
        float4 d0 = make_float4(0.f, 0.f, 0.f, 0.f);
        float4 d1 = make_float4(0.f, 0.f, 0.f, 0.f);
        if (gm >= 59) {
            const float* xa = xrow + (size_t)(gm - 58) * CC;
            const float* xb = xrow + (size_t)(gm - 59) * CC;
            float4 a0 = *(const float4*)xa, a1 = *(const float4*)(xa + 4);
            float4 b0 = *(const float4*)xb, b1 = *(const float4*)(xb + 4);
            d0.x = a0.x - b0.x; d0.y = a0.y - b0.y; d0.z = a0.z - b0.z; d0.w = a0.w - b0.w;
            d1.x = a1.x - b1.x; d1.y = a1.y - b1.y; d1.z = a1.z - b1.z; d1.w = a1.w - b1.w;
        }
        float* vv = vbuf + m * 12;
        vv[0] = inv59;
        vv[1] = d0.x; vv[2] = d0.y; vv[3] = d0.z; vv[4] = d0.w;
        vv[5] = d1.x; vv[6] = d1.y; vv[7] = d1.z; vv[8] = d1.w;
    }
    __syncwarp();

    const int li = lane / 3;
    const int jb = (lane % 3) * 3;

    float S3r[3][9];
    float S2r[3];
    float s1f[9];
    if (lane < 27) {
#pragma unroll
        for (int c = 0; c < 3; c++) {
            S2r[c] = 0.0f;
#pragma unroll
            for (int k = 0; k < 9; k++) S3r[c][k] = 0.0f;
        }
#pragma unroll
        for (int k = 0; k < 9; k++) s1f[k] = 0.0f;

        // ---- bootstrap: 59 right-steps -> R(ws) ----
#pragma unroll 2
        for (int step = 0; step < 59; step++) {
            const float* vv = vbuf + step * 12;
            float vi = vv[li];
            float bco = fmaf(vi, 1.0f / 6.0f, 0.5f * s1f[li]);
            float cco = fmaf(vi, 0.5f, s1f[li]);
#pragma unroll
            for (int c = 0; c < 3; c++) {
                float vj = vv[jb + c];
                float a = fmaf(bco, vj, S2r[c]);
#pragma unroll
                for (int k = 0; k < 9; k++) S3r[c][k] = fmaf(a, vv[k], S3r[c][k]);
                S2r[c] = fmaf(cco, vj, S2r[c]);
            }
#pragma unroll
            for (int k = 0; k < 9; k++) s1f[k] += vv[k];
        }
        // publish R.S2
#pragma unroll
        for (int c = 0; c < 3; c++) s2s[li * 9 + jb + c] = S2r[c];
    }
    __syncwarp();

    for (int widx = 0; widx < WPW; widx++) {
        const int ssg = ws + widx;     // output row n
        const int ssr = wsr + widx;

        // ---- build W = exp(v0) (x) R into extract buffers ----
        {
            int p0 = ssr - 59; if (p0 < 0) p0 = 0;
            const float* xv = xrow + (size_t)p0 * CC;
            float v0[9];
            v0[0] = 0.0f;
            float4 a0 = *(const float4*)xv, a1 = *(const float4*)(xv + 4);
            v0[1] = a0.x; v0[2] = a0.y; v0[3] = a0.z; v0[4] = a0.w;
            v0[5] = a1.x; v0[6] = a1.y; v0[7] = a1.z; v0[8] = a1.w;
            if (lane < 27) {
                float A = v0[li];
#pragma unroll
                for (int c = 0; c < 3; c++) {
                    int j = jb + c;
                    float B = A * v0[j];
                    s2w[li * 9 + j] = S2r[c] + A * s1f[j] + 0.5f * B;
                    const float* rowj = s2s + j * 9;
                    float* o = s3w + (li * 9 + j) * 9;
                    float Bh = 0.5f * B;
                    float B6 = B * (1.0f / 6.0f);
#pragma unroll
                    for (int k = 0; k < 9; k++)
                        o[k] = S3r[c][k] + A * rowj[k] + Bh * s1f[k] + B6 * v0[k];
                }
                if (lane < 9) s1w[lane] = s1f[lane] + v0[lane];
            }
        }
        __syncwarp();

        // ---- log-sig + Lyndon extraction (all 32 lanes) ----
        if (lane < 9) feat_store(ssg, lane, s1w[lane]);
        for (int t = lane; t < 36; t += 32) {
            int e = c_tab.l2[t];
            int i = e / 9, j = e % 9;
            feat_store(ssg, 9 + t, s2w[e] - 0.5f * s1w[i] * s1w[j]);
        }
        for (int t = lane; t < 240; t += 32) {
            int e  = c_tab.l3[t];
            int k  = e % 9;
            int ij = e / 9;
            int j  = ij % 9;
            int i  = ij / 9;
            float v = s3w[e]
                    - 0.5f * (s1w[i] * s2w[j * 9 + k] + s2w[ij] * s1w[k])
                    + s1w[i] * s1w[j] * s1w[k] * (1.0f / 3.0f);
            feat_store(ssg, 45 + t, v);
        }
        for (int t = SIGCH + lane; t < KP1; t += 32) {
            g_fhi[(size_t)ssg * KP1 + t] = __float2bfloat16(0.0f);
            g_flo[(size_t)ssg * KP1 + t] = __float2bfloat16(0.0f);
        }
        __syncwarp();

        if (widx == WPW - 1) break;

        // ---- slide: left-remove G[ss], right-append G[ss+59] ----
        if (lane < 27) {
            // LEFT: u = -G[ss]  (uses old S1 regs + old S2 mirror in s2s)
            const float* vo = vbuf + widx * 12;
            float A = -vo[li];
#pragma unroll
            for (int c = 0; c < 3; c++) {
                int j = jb + c;
                float B  = A * (-vo[j]);
                float Bh = 0.5f * B;
                float B6 = B * (1.0f / 6.0f);
                const float* rowj = s2s + j * 9;
#pragma unroll
                for (int k = 0; k < 9; k++)
                    S3r[c][k] += A * rowj[k] + Bh * s1f[k] + B6 * (-vo[k]);
                S2r[c] += A * s1f[j] + Bh;
            }
#pragma unroll
            for (int k = 0; k < 9; k++) s1f[k] -= vo[k];

            // RIGHT: v = G[ss+59]
            const float* vn = vbuf + (widx + 59) * 12;
            float vi = vn[li];
            float bco = fmaf(vi, 1.0f / 6.0f, 0.5f * s1f[li]);
            float cco = fmaf(vi, 0.5f, s1f[li]);
#pragma unroll
            for (int c = 0; c < 3; c++) {
                float vj = vn[jb + c];
                float a = fmaf(bco, vj, S2r[c]);
#pragma unroll
                for (int k = 0; k < 9; k++) S3r[c][k] = fmaf(a, vn[k], S3r[c][k]);
                S2r[c] = fmaf(cco, vj, S2r[c]);
            }
#pragma unroll
            for (int k = 0; k < 9; k++) s1f[k] += vn[k];

            // publish new R.S2
#pragma unroll
            for (int c = 0; c < 3; c++) s2s[li * 9 + jb + c] = S2r[c];
        }
        __syncwarp();
    }
}

// ---------------------------------------------------------------------------
// FUSED MLP (unchanged from R15): phase1 (64x512 split-bf16 MMA + GELU + LN
// -> h in SMEM), phase2 (64x256 split-bf16 MMA from smem h, w2 streamed).
// ---------------------------------------------------------------------------
#define G1_AS    40
#define G1_BS    520
#define G1_A_HI  0
#define G1_A_LO  (G1_A_HI + 64 * G1_AS * 2)
#define G1_B_HI  (G1_A_LO + 64 * G1_AS * 2)
#define G1_B_LO  (G1_B_HI + 32 * G1_BS * 2)
#define G1_BUFSZ (G1_B_LO + 32 * G1_BS * 2)
#define HSH      520
#define F_H_HI   0
#define F_H_LO   (64 * HSH * 2)
#define W2_HI    0
#define W2_LO    16896
#define W2_BUFSZ 33792
#define F_W2     153600
#define F_B1S    221184
#define F_LNG    (F_B1S + 2048)
#define F_LNB    (F_LNG + 2048)
#define F_RS     (F_LNB + 2048)
#define F_RQ     (F_RS + 2048)
#define F_MU     (F_RQ + 2048)
#define F_RSD    (F_MU + 256)
#define SMEM_F   (F_RSD + 256)

__device__ __forceinline__ void g1_stage(uint32_t sbuf, int row0, int ch, int tid) {
    {
        int arr = tid >> 8, idx = tid & 255;
        int r = idx >> 2, q = idx & 3;
        const __nv_bfloat16* src = arr ? g_flo : g_fhi;
        cpa16(sbuf + (arr ? G1_A_LO : G1_A_HI) + (uint32_t)(r * G1_AS + q * 8) * 2,
              (const char*)src + ((size_t)(row0 + r) * KP1 + ch * 32 + q * 8) * 2);
    }
#pragma unroll
    for (int it = tid; it < 4096; it += 512) {
        int arr = it >> 11, idx = it & 2047;
        int r = idx >> 6, c = idx & 63;
        const __nv_bfloat16* src = arr ? g_w1lo : g_w1hi;
        cpa16(sbuf + (arr ? G1_B_LO : G1_B_HI) + (uint32_t)(r * G1_BS + c * 8) * 2,
              (const char*)src + ((size_t)(ch * 32 + r) * H2C + c * 8) * 2);
    }
}

__device__ __forceinline__ void w2_stage(uint32_t sbuf, int ch, int tid) {
#pragma unroll
    for (int it = tid; it < 2048; it += 512) {
        int arr = it >> 10, idx = it & 1023;
        int r = idx >> 5, c = idx & 31;
        const __nv_bfloat16* src = arr ? g_w2lo : g_w2hi;
        cpa16(sbuf + (arr ? W2_LO : W2_HI) + (uint32_t)(r * 264 + c * 8) * 2,
              (const char*)src + ((size_t)(ch * 32 + r) * H1C + c * 8) * 2);
    }
}

__global__ __launch_bounds__(512, 1) void mlp_fused_kernel(
    const float* __restrict__ b1, const float* __restrict__ lng,
    const float* __restrict__ lnb, const float* __restrict__ b2,
    float* __restrict__ out)
{
    extern __shared__ char smem[];
    const uint32_t sb = smem_u32(smem);
    const int tid  = threadIdx.x;
    const int lane = tid & 31;
    const int wid  = tid >> 5;
    const int wm   = wid >> 3;
    const int wn   = wid & 7;
    const int row0 = blockIdx.x * 64;

    float* b1s  = (float*)(smem + F_B1S);
    float* lngs = (float*)(smem + F_LNG);
    float* lnbs = (float*)(smem + F_LNB);
    float* reds = (float*)(smem + F_RS);
    float* redq = (float*)(smem + F_RQ);
    float* mus  = (float*)(smem + F_MU);
    float* rsd  = (float*)(smem + F_RSD);
    for (int i = tid; i < H2C; i += 512) {
        b1s[i] = b1[i]; lngs[i] = lng[i]; lnbs[i] = lnb[i];
    }

    const int mi = lane >> 3, ri = lane & 7;
    const uint32_t aA = ((uint32_t)((wm * 32 + ri + ((mi & 1) << 3)) * G1_AS
                                    + ((mi >> 1) << 3))) * 2;
    const uint32_t aB = ((uint32_t)((ri + ((mi & 1) << 3)) * G1_BS
                                    + wn * 64 + ((mi >> 1) << 3))) * 2;

    float acc[2][8][4];
#pragma unroll
    for (int m = 0; m < 2; m++)
#pragma unroll
        for (int n = 0; n < 8; n++)
#pragma unroll
            for (int e = 0; e < 4; e++) acc[m][n][e] = 0.0f;

    g1_stage(sb, row0, 0, tid);
    cpa_commit();

    for (int ch = 0; ch < 9; ch++) {
        if (ch + 1 < 9) {
            g1_stage(sb + ((ch + 1) & 1) * G1_BUFSZ, row0, ch + 1, tid);
            cpa_commit();
            cpa_wait<1>();
        } else {
            cpa_wait<0>();
        }
        __syncthreads();

        const uint32_t base = sb + (ch & 1) * G1_BUFSZ;
#pragma unroll
        for (int ks = 0; ks < 2; ks++) {
            uint32_t ah[2][4], al[2][4];
#pragma unroll
            for (int ma = 0; ma < 2; ma++) {
                uint32_t off = aA + (ma * 16 * G1_AS + ks * 16) * 2;
                ldmx4(ah[ma], base + G1_A_HI + off);
                ldmx4(al[ma], base + G1_A_LO + off);
            }
#pragma unroll
            for (int pn = 0; pn < 4; pn++) {
                uint32_t bh[4], bl[4];
                uint32_t off = aB + (ks * 16 * G1_BS + pn * 16) * 2;
                ldmx4t(bh, base + G1_B_HI + off);
                ldmx4t(bl, base + G1_B_LO + off);
#pragma unroll
                for (int ma = 0; ma < 2; ma++) {
#pragma unroll
                    for (int nn = 0; nn < 2; nn++) {
                        float* d = acc[ma][pn * 2 + nn];
                        mma16816(d, ah[ma], bh[nn * 2], bh[nn * 2 + 1]);
                        mma16816(d, al[ma], bh[nn * 2], bh[nn * 2 + 1]);
                        mma16816(d, ah[ma], bl[nn * 2], bl[nn * 2 + 1]);
                    }
                }
            }
        }
        __syncthreads();
    }

    w2_stage(sb + F_W2, 0, tid);
    cpa_commit();

    float s1v[2][2] = {{0.f, 0.f}, {0.f, 0.f}};
    float s2v[2][2] = {{0.f, 0.f}, {0.f, 0.f}};
#pragma unroll
    for (int ma = 0; ma < 2; ma++)
#pragma unroll
        for (int na = 0; na < 8; na++) {
            int col = wn * 64 + na * 8 + (lane & 3) * 2;
#pragma unroll
            for (int e = 0; e < 4; e++) {
                float v = gelu_exact(acc[ma][na][e] + b1s[col + (e & 1)]);
                acc[ma][na][e] = v;
                s1v[ma][e >> 1] += v;
                s2v[ma][e >> 1] = fmaf(v, v, s2v[ma][e >> 1]);
            }
        }
#pragma unroll
    for (int off = 1; off <= 2; off <<= 1) {
#pragma unroll
        for (int ma = 0; ma < 2; ma++)
#pragma unroll
            for (int h = 0; h < 2; h++) {
                s1v[ma][h] += __shfl_xor_sync(0xffffffffu, s1v[ma][h], off);
                s2v[ma][h] += __shfl_xor_sync(0xffffffffu, s2v[ma][h], off);
            }
    }
    if ((lane & 3) == 0) {
#pragma unroll
        for (int ma = 0; ma < 2; ma++)
#pragma unroll
            for (int h = 0; h < 2; h++) {
                int row = wm * 32 + ma * 16 + h * 8 + (lane >> 2);
                reds[row * 8 + wn] = s1v[ma][h];
                redq[row * 8 + wn] = s2v[ma][h];
            }
    }
    __syncthreads();
    float* b2s = b1s;
    for (int i = tid; i < H1C; i += 512) b2s[i] = b2[i];
    if (tid < 64) {
        float s = 0.f, q = 0.f;
#pragma unroll
        for (int w = 0; w < 8; w++) { s += reds[tid * 8 + w]; q += redq[tid * 8 + w]; }
        float mu  = s * (1.0f / 512.0f);
        float var = q * (1.0f / 512.0f) - mu * mu;
        mus[tid] = mu;
        rsd[tid] = rsqrtf(var + 1e-5f);
    }
    __syncthreads();

#pragma unroll
    for (int ma = 0; ma < 2; ma++)
#pragma unroll
        for (int h = 0; h < 2; h++) {
            int row = wm * 32 + ma * 16 + h * 8 + (lane >> 2);
            float mu = mus[row], rs = rsd[row];
#pragma unroll
            for (int na = 0; na < 8; na++) {
                int col = wn * 64 + na * 8 + (lane & 3) * 2;
                float y0 = fmaf((acc[ma][na][h * 2]     - mu) * rs, lngs[col],     lnbs[col]);
                float y1 = fmaf((acc[ma][na][h * 2 + 1] - mu) * rs, lngs[col + 1], lnbs[col + 1]);
                __nv_bfloat16 h0 = __float2bfloat16(y0), h1 = __float2bfloat16(y1);
                float f0 = __bfloat162float(h0), f1 = __bfloat162float(h1);
                uint32_t off = (uint32_t)(row * HSH + col) * 2;
                *(uint32_t*)(smem + F_H_HI + off) = pkbf2(f0, f1);
                *(uint32_t*)(smem + F_H_LO + off) = pkbf2(y0 - f0, y1 - f1);
            }
        }
    __syncthreads();

    float ac2[2][4][4];
#pragma unroll
    for (int m = 0; m < 2; m++)
#pragma unroll
        for (int n = 0; n < 4; n++)
#pragma unroll
            for (int e = 0; e < 4; e++) ac2[m][n][e] = 0.0f;

    const uint32_t aB2 = ((uint32_t)((ri + ((mi & 1) << 3)) * 264
                                     + wn * 32 + ((mi >> 1) << 3))) * 2;
    const uint32_t aA2row = (uint32_t)(wm * 32 + ri + ((mi & 1) << 3));
    const uint32_t aA2col = (uint32_t)((mi >> 1) << 3);

    for (int ch = 0; ch < 16; ch++) {
        if (ch + 1 < 16) {
            w2_stage(sb + F_W2 + ((ch + 1) & 1) * W2_BUFSZ, ch + 1, tid);
            cpa_commit();
            cpa_wait<1>();
        } else {
            cpa_wait<0>();
        }
        __syncthreads();

        const uint32_t wb = sb + F_W2 + (ch & 1) * W2_BUFSZ;
#pragma unroll
        for (int ks = 0; ks < 2; ks++) {
            uint32_t ah[2][4], al[2][4];
#pragma unroll
            for (int ma = 0; ma < 2; ma++) {
                uint32_t off = ((aA2row + ma * 16) * HSH
                                + ch * 32 + ks * 16 + aA2col) * 2;
                ldmx4(ah[ma], sb + F_H_HI + off);
                ldmx4(al[ma], sb + F_H_LO + off);
            }
#pragma unroll
            for (int pn = 0; pn < 2; pn++) {
                uint32_t bh[4], bl[4];
                uint32_t off = aB2 + (ks * 16 * 264 + pn * 16) * 2;
                ldmx4t(bh, wb + W2_HI + off);
                ldmx4t(bl, wb + W2_LO + off);
#pragma unroll
                for (int ma = 0; ma < 2; ma++) {
#pragma unroll
                    for (int nn = 0; nn < 2; nn++) {
                        float* d = ac2[ma][pn * 2 + nn];
                        mma16816(d, ah[ma], bh[nn * 2], bh[nn * 2 + 1]);
                        mma16816(d, al[ma], bh[nn * 2], bh[nn * 2 + 1]);
                        mma16816(d, ah[ma], bl[nn * 2], bl[nn * 2 + 1]);
                    }
                }
            }
        }
        __syncthreads();
    }

#pragma unroll
    for (int ma = 0; ma < 2; ma++)
#pragma unroll
        for (int h = 0; h < 2; h++) {
            int row = wm * 32 + ma * 16 + h * 8 + (lane >> 2);
            float* op = out + (size_t)(row0 + row) * H1C;
#pragma unroll
            for (int na = 0; na < 4; na++) {
                int col = wn * 32 + na * 8 + (lane & 3) * 2;
                float2 v;
                v.x = ac2[ma][na][h * 2]     + b2s[col];
                v.y = ac2[ma][na][h * 2 + 1] + b2s[col + 1];
                *(float2*)(op + col) = v;
            }
        }
}

// ---------------------------------------------------------------------------
// Launch
// ---------------------------------------------------------------------------
extern "C" void kernel_launch(void* const* d_in, const int* in_sizes, int n_in,
                              void* d_out, int out_size) {
    const float* x   = (const float*)d_in[0];
    const float* w1  = (const float*)d_in[1];
    const float* b1  = (const float*)d_in[2];
    const float* lng = (const float*)d_in[3];
    const float* lnb = (const float*)d_in[4];
    const float* w2  = (const float*)d_in[5];
    const float* b2  = (const float*)d_in[6];
    float* out = (float*)d_out;

    cudaFuncSetAttribute(sig_kernel,
                         cudaFuncAttributeMaxDynamicSharedMemorySize, SIG_SMEM);
    cudaFuncSetAttribute(mlp_fused_kernel,
                         cudaFuncAttributeMaxDynamicSharedMemorySize, SMEM_F);

    prep_kernel<<<(KP1 * H2C + H2C * H1C + 255) / 256, 256>>>(w1, w2);
    sig_kernel<<<NTOT / (SIG_WARPS * WPW), 256, SIG_SMEM>>>(x);
    mlp_fused_kernel<<<NTOT / 64, 512, SMEM_F>>>(b1, lng, lnb, b2, out);
}